// round 1
// baseline (speedup 1.0000x reference)
#include <cuda_runtime.h>
#include <cstdint>

// ScaledDotProductAttention: B=4, H=16, S=2048, D=64, fp32.
// Reference quirk: scores = (Q@K^T) * 4096 -> softmax is near-one-hot.
// exp(4096*(s-m)) underflows fp32 for s < m - 0.0215, so per query only
// keys within a 0.0215 window of the running max ever contribute.
// => compute fp32-exact QK^T (packed f32x2 FMAs), and take a rare branch
//    (~8/2048 keys) for exp / rescale / V accumulation.

#define S_LEN 2048
#define HDIM  64
#define N_BH  64
#define TQ    128   // queries per CTA (1 thread per query)
#define TK    128   // keys per smem tile
#define WINDOW 0.03f
#define LOGIT_SCALE 4096.0f

typedef unsigned long long u64;

__device__ __forceinline__ u64 ffma2(u64 a, u64 b, u64 c) {
    u64 d;
    asm("fma.rn.f32x2 %0, %1, %2, %3;" : "=l"(d) : "l"(a), "l"(b), "l"(c));
    return d;
}
__device__ __forceinline__ u64 fadd2(u64 a, u64 b) {
    u64 d;
    asm("add.rn.f32x2 %0, %1, %2;" : "=l"(d) : "l"(a), "l"(b));
    return d;
}
__device__ __forceinline__ u64 fmul2(u64 a, u64 b) {
    u64 d;
    asm("mul.rn.f32x2 %0, %1, %2;" : "=l"(d) : "l"(a), "l"(b));
    return d;
}
__device__ __forceinline__ float hsum2(u64 a) {
    float x, y;
    asm("mov.b64 {%0, %1}, %2;" : "=f"(x), "=f"(y) : "l"(a));
    return x + y;
}
__device__ __forceinline__ u64 pack2(float x, float y) {
    u64 d;
    asm("mov.b64 %0, {%1, %2};" : "=l"(d) : "f"(x), "f"(y));
    return d;
}

__global__ void __launch_bounds__(TQ, 2)
sdpa_onehot_kernel(const float* __restrict__ Q,
                   const float* __restrict__ K,
                   const float* __restrict__ V,
                   float* __restrict__ O) {
    __shared__ float sK[TK * HDIM];  // 32 KB

    const int bh  = blockIdx.y;
    const int tid = threadIdx.x;
    const long qidx = (long)bh * S_LEN + (long)blockIdx.x * TQ + tid;

    // Load this thread's Q row into 32 packed f32x2 registers.
    const u64* qg = (const u64*)(Q + qidx * HDIM);
    u64 q2[HDIM / 2];
#pragma unroll
    for (int j = 0; j < HDIM / 2; j++) q2[j] = qg[j];

    // Output accumulator (packed), online-softmax state.
    u64 o2[HDIM / 2];
#pragma unroll
    for (int j = 0; j < HDIM / 2; j++) o2[j] = 0ULL;  // (0.0f, 0.0f)
    float m = -INFINITY;
    float l = 0.0f;

    const float* kbase = K + (long)bh * S_LEN * HDIM;
    const float* vbase = V + (long)bh * S_LEN * HDIM;

    for (int kt = 0; kt < S_LEN / TK; kt++) {
        __syncthreads();  // previous tile fully consumed
        // Cooperative, coalesced K-tile load: TK*HDIM floats = 2048 float4.
        {
            const float4* gk = (const float4*)(kbase + (long)kt * TK * HDIM);
            float4* s4 = (float4*)sK;
#pragma unroll
            for (int i = 0; i < (TK * HDIM / 4) / TQ; i++)
                s4[tid + i * TQ] = gk[tid + i * TQ];
        }
        __syncthreads();

#pragma unroll 1
        for (int kk = 0; kk < TK; kk++) {
            // fp32-exact dot(Q_row, K_row) via 4 independent packed FMA chains.
            const u64* k2 = (const u64*)(sK + kk * HDIM);
            u64 a0 = 0ULL, a1 = 0ULL, a2 = 0ULL, a3 = 0ULL;
#pragma unroll
            for (int j = 0; j < 8; j++) {
                a0 = ffma2(q2[4 * j + 0], k2[4 * j + 0], a0);
                a1 = ffma2(q2[4 * j + 1], k2[4 * j + 1], a1);
                a2 = ffma2(q2[4 * j + 2], k2[4 * j + 2], a2);
                a3 = ffma2(q2[4 * j + 3], k2[4 * j + 3], a3);
            }
            float s = hsum2(fadd2(fadd2(a0, a1), fadd2(a2, a3)));

            // Rare path: only keys within the fp32-underflow window of the
            // running max can contribute any weight (> ~1e-54 here).
            if (s > m - WINDOW) {
                float w;
                if (s > m) {
                    float r = __expf(LOGIT_SCALE * (m - s));  // 0 on first hit
                    l *= r;
                    u64 r2 = pack2(r, r);
#pragma unroll
                    for (int j = 0; j < HDIM / 2; j++) o2[j] = fmul2(o2[j], r2);
                    m = s;
                    w = 1.0f;
                } else {
                    w = __expf(LOGIT_SCALE * (s - m));
                }
                l += w;
                const u64* v2 = (const u64*)(vbase + (long)(kt * TK + kk) * HDIM);
                u64 w2 = pack2(w, w);
#pragma unroll
                for (int j = 0; j < HDIM / 2; j++) o2[j] = ffma2(w2, v2[j], o2[j]);
            }
        }
    }

    // Normalize and store.
    float inv = 1.0f / l;
    u64 inv2 = pack2(inv, inv);
    u64* og = (u64*)(O + qidx * HDIM);
#pragma unroll
    for (int j = 0; j < HDIM / 2; j++) og[j] = fmul2(o2[j], inv2);
}

extern "C" void kernel_launch(void* const* d_in, const int* in_sizes, int n_in,
                              void* d_out, int out_size) {
    const float* Q = (const float*)d_in[0];
    const float* K = (const float*)d_in[1];
    const float* V = (const float*)d_in[2];
    float* O = (float*)d_out;

    dim3 grid(S_LEN / TQ, N_BH);  // (16, 64)
    dim3 block(TQ);
    sdpa_onehot_kernel<<<grid, block>>>(Q, K, V, O);
}